// round 6
// baseline (speedup 1.0000x reference)
#include <cuda_runtime.h>
#include <cuda_bf16.h>
#include <math.h>

// Problem constants (fixed by reference setup_inputs)
#define NN 100000      // nodes
#define NE 1600000     // edges
#define NG 256         // graphs
#define NH 256         // hidden
#define NF 7           // extra graph features
#define H1 128         // MLP hidden
#define BN_EPS 1e-5f
#define NC_BLOCKS 2048
#define NC_THREADS 128
#define TILE 64        // chunk = ceil(NN/NC_BLOCKS) = 49 <= 64

typedef unsigned long long ull;

// ---------------- packed f32x2 helpers (sm_100a+ FFMA2 path) -----------------
__device__ __forceinline__ ull pk2(float lo, float hi) {
    ull r; asm("mov.b64 %0, {%1,%2};" : "=l"(r) : "f"(lo), "f"(hi)); return r;
}
__device__ __forceinline__ void unpk2(float& lo, float& hi, ull a) {
    asm("mov.b64 {%0,%1}, %2;" : "=f"(lo), "=f"(hi) : "l"(a));
}
#define FMA2(d,a,b,c) asm("fma.rn.f32x2 %0, %1, %2, %3;" : "=l"(d) : "l"(a), "l"(b), "l"(c))
#define MUL2(d,a,b)   asm("mul.rn.f32x2 %0, %1, %2;"     : "=l"(d) : "l"(a), "l"(b))
#define ADD2(d,a,b)   asm("add.rn.f32x2 %0, %1, %2;"     : "=l"(d) : "l"(a), "l"(b))
#define ABS2(d,a)     asm("and.b64 %0, %1, 0x7FFFFFFF7FFFFFFF;" : "=l"(d) : "l"(a))

// ---------------- scratch (device globals, zero-initialized at module load;
// the mlp kernel re-zeroes everything dirtied so every call sees zeros) -------
__device__ int   g_degi[NN];    // edge count per dst (self-loop added later)
__device__ float g_dinv[NN];    // rsqrt(deg+1)
__device__ float g_p[NN];       // dinv * x
__device__ float g_t[NN];       // sum over incoming edges of p[src]
__device__ float g_S[NG * NH];  // per-graph per-channel sums of u
__device__ float g_sumsq[NH];   // sum of u^2
__device__ float g_scale[NH];   // BN scale = gamma * rsqrt(var+eps)
__device__ float g_shift[NH];   // BN shift = beta - mean*scale
__device__ float g_cnt[NG];     // nodes per graph
__device__ unsigned int g_arrive;  // last-block arrival counter

// exact gelu (MLP tail only — tiny, keep max accuracy)
__device__ __forceinline__ float gelu_f(float z) {
    return 0.5f * z * (1.0f + erff(z * 0.70710678118654752f));
}

// ---------------- kernels ----------------------------------------------------

// degree histogram: 16 edges per thread, int atomics
__global__ void deg_kernel(const int* __restrict__ dst) {
    int base = (blockIdx.x * blockDim.x + threadIdx.x) * 16;
    if (base + 16 <= NE) {
        int4 a = *reinterpret_cast<const int4*>(dst + base);
        int4 b = *reinterpret_cast<const int4*>(dst + base + 4);
        int4 c = *reinterpret_cast<const int4*>(dst + base + 8);
        int4 d = *reinterpret_cast<const int4*>(dst + base + 12);
        atomicAdd(&g_degi[a.x], 1); atomicAdd(&g_degi[a.y], 1);
        atomicAdd(&g_degi[a.z], 1); atomicAdd(&g_degi[a.w], 1);
        atomicAdd(&g_degi[b.x], 1); atomicAdd(&g_degi[b.y], 1);
        atomicAdd(&g_degi[b.z], 1); atomicAdd(&g_degi[b.w], 1);
        atomicAdd(&g_degi[c.x], 1); atomicAdd(&g_degi[c.y], 1);
        atomicAdd(&g_degi[c.z], 1); atomicAdd(&g_degi[c.w], 1);
        atomicAdd(&g_degi[d.x], 1); atomicAdd(&g_degi[d.y], 1);
        atomicAdd(&g_degi[d.z], 1); atomicAdd(&g_degi[d.w], 1);
    }
}

__global__ void node_prep_kernel(const float* __restrict__ x) {
    int i = blockIdx.x * blockDim.x + threadIdx.x;
    if (i < NN) {
        float dv = rsqrtf((float)(g_degi[i] + 1));   // +1 = self loop
        g_dinv[i] = dv;
        g_p[i] = dv * x[i];
    }
}

// t[dst] += p[src]; 8 edges per thread, gathers batched before atomics
__global__ void scatter_kernel(const int* __restrict__ src, const int* __restrict__ dst) {
    int base = (blockIdx.x * blockDim.x + threadIdx.x) * 8;
    if (base + 8 <= NE) {
        int4 s0 = *reinterpret_cast<const int4*>(src + base);
        int4 s1 = *reinterpret_cast<const int4*>(src + base + 4);
        int4 d0 = *reinterpret_cast<const int4*>(dst + base);
        int4 d1 = *reinterpret_cast<const int4*>(dst + base + 4);
        float p0 = g_p[s0.x], p1 = g_p[s0.y], p2 = g_p[s0.z], p3 = g_p[s0.w];
        float p4 = g_p[s1.x], p5 = g_p[s1.y], p6 = g_p[s1.z], p7 = g_p[s1.w];
        atomicAdd(&g_t[d0.x], p0); atomicAdd(&g_t[d0.y], p1);
        atomicAdd(&g_t[d0.z], p2); atomicAdd(&g_t[d0.w], p3);
        atomicAdd(&g_t[d1.x], p4); atomicAdd(&g_t[d1.y], p5);
        atomicAdd(&g_t[d1.z], p6); atomicAdd(&g_t[d1.w], p7);
    }
}

// Big O(N*H) kernel, fully packed f32x2: u[n][{c0,c1}] = gelu(s_n*W+b).
// With y = z/sqrt(2):  gelu(z) = (sqrt2/2) * (y + |y|*erf(|y|)),
// erf via Abramowitz-Stegun 7.1.26 (max abs err 1.5e-7).
// Per-graph sums via run-length flushing (batch sorted) + sumsq for BN.
// Last arriving block computes BN scale/shift (mean from per-graph sums),
// plus per-graph counts.
__global__ __launch_bounds__(NC_THREADS) void node_channel_kernel(
    const int* __restrict__ batch,
    const float* __restrict__ W_conv,
    const float* __restrict__ b_conv,
    const float* __restrict__ gamma,
    const float* __restrict__ beta)
{
    int c0 = threadIdx.x;            // channel pair (c0, c0+128)
    int c1 = c0 + NC_THREADS;
    const int chunk = (NN + NC_BLOCKS - 1) / NC_BLOCKS;   // 49
    int start = blockIdx.x * chunk;
    int end = min(start + chunk, NN);

    __shared__ float2 sh[TILE];

    if (start < end) {
        const float is2 = 0.70710678118654752f;     // 1/sqrt(2)
        ull wq = pk2(W_conv[c0] * is2, W_conv[c1] * is2);
        ull bq = pk2(b_conv[c0] * is2, b_conv[c1] * is2);
        const ull one2   = pk2(1.0f, 1.0f);
        const ull pc2    = pk2(0.3275911f, 0.3275911f);
        const ull nl2e2  = pk2(-1.4426950408889634f, -1.4426950408889634f);
        const ull c2     = pk2(is2, is2);
        // negated A-S coefficients (so poly gives -p directly)
        const ull na5 = pk2(-1.061405429f, -1.061405429f);
        const ull na4 = pk2( 1.453152027f,  1.453152027f);
        const ull na3 = pk2(-1.421413741f, -1.421413741f);
        const ull na2 = pk2( 0.284496736f,  0.284496736f);
        const ull na1 = pk2(-0.254829592f, -0.254829592f);

        // stage tile: s_n = dinv*t + dinv^2*x  (g_p = dinv*x), plus batch id
        int n = start + c0;
        if (c0 < end - start) {
            float dv = g_dinv[n];
            sh[c0] = make_float2(dv * (g_t[n] + g_p[n]),
                                 __int_as_float(batch[n]));
        }
        __syncthreads();

        ull acc = 0ull, sq = 0ull;   // packed (c0,c1) accumulators (0.0f,0.0f)
        int cur = __float_as_int(sh[0].y);
        int len = end - start;

        #pragma unroll 4
        for (int k = 0; k < len; k++) {
            float2 v = sh[k];
            int g = __float_as_int(v.y);        // uniform across warp
            if (g != cur) {                     // rare (~0.3/chunk)
                float a0, a1; unpk2(a0, a1, acc);
                atomicAdd(&g_S[cur * NH + c0], a0);
                atomicAdd(&g_S[cur * NH + c1], a1);
                acc = 0ull;
                cur = g;
            }
            ull s2 = pk2(v.x, v.x);
            ull y;    FMA2(y, s2, wq, bq);      // y = z/sqrt2 for both channels
            ull ax;   ABS2(ax, y);              // X = |y|
            ull xx;   MUL2(xx, ax, ax);
            ull ea;   MUL2(ea, xx, nl2e2);      // -X^2*log2(e)
            ull d;    FMA2(d, ax, pc2, one2);   // 1 + p*X
            float d0, d1;  unpk2(d0, d1, d);
            float e0, e1;  unpk2(e0, e1, ea);
            float t0, t1;
            asm("rcp.approx.f32 %0, %1;" : "=f"(t0) : "f"(d0));
            asm("rcp.approx.f32 %0, %1;" : "=f"(t1) : "f"(d1));
            asm("ex2.approx.f32 %0, %1;" : "=f"(e0) : "f"(e0));
            asm("ex2.approx.f32 %0, %1;" : "=f"(e1) : "f"(e1));
            ull t = pk2(t0, t1);
            ull e = pk2(e0, e1);
            ull p;  FMA2(p, t, na5, na4);       // negated Horner
            FMA2(p, p, t, na3);
            FMA2(p, p, t, na2);
            FMA2(p, p, t, na1);
            MUL2(p, p, t);                      // p = -poly(t)
            ull r;  FMA2(r, p, e, one2);        // erf(X) = 1 - poly*e
            ull t2; FMA2(t2, ax, r, y);         // y + X*erf(X)
            ull u;  MUL2(u, t2, c2);            // gelu values (c0,c1)
            ADD2(acc, acc, u);
            FMA2(sq, u, u, sq);
        }
        float a0, a1, q0, q1;
        unpk2(a0, a1, acc); unpk2(q0, q1, sq);
        atomicAdd(&g_S[cur * NH + c0], a0);
        atomicAdd(&g_S[cur * NH + c1], a1);
        atomicAdd(&g_sumsq[c0], q0);
        atomicAdd(&g_sumsq[c1], q1);
    }

    // ---- last-block epilogue: BN stats + per-graph counts ----
    __threadfence();
    __shared__ unsigned int s_last;
    if (c0 == 0)
        s_last = (atomicAdd(&g_arrive, 1u) == (unsigned)(gridDim.x - 1));
    __syncthreads();
    if (s_last) {
        const float invN = 1.0f / (float)NN;
        #pragma unroll
        for (int cc = 0; cc < 2; cc++) {
            int c = c0 + cc * NC_THREADS;
            float tot = 0.0f;                   // mean from per-graph sums
            #pragma unroll 8
            for (int g = 0; g < NG; g++) tot += g_S[g * NH + c];
            float mean = tot * invN;
            float var  = g_sumsq[c] * invN - mean * mean;
            float sc   = rsqrtf(var + BN_EPS) * gamma[c];
            g_scale[c] = sc;
            g_shift[c] = beta[c] - mean * sc;

            // nodes with batch[n] == c (c doubles as graph id)
            int lo = 0, hi = NN;
            while (lo < hi) { int m = (lo + hi) >> 1; if (batch[m] < c) lo = m + 1; else hi = m; }
            int lb = lo;
            hi = NN;
            while (lo < hi) { int m = (lo + hi) >> 1; if (batch[m] < c + 1) lo = m + 1; else hi = m; }
            g_cnt[c] = (float)(lo - lb);
        }
        if (c0 == 0) g_arrive = 0;   // reset for next call
    }
}

// MLP tail: one block per graph, 128 threads; also re-zeroes all scratch.
__global__ __launch_bounds__(H1) void mlp_kernel(
    const float* __restrict__ y_feat,
    const float* __restrict__ W1, const float* __restrict__ b1,
    const float* __restrict__ W2, const float* __restrict__ b2,
    float* __restrict__ out)
{
    int g = blockIdx.x;
    int j = threadIdx.x;

    __shared__ float sh_in[NH + NF];
    __shared__ float sh_h[H1];

    float cnt = fmaxf(g_cnt[g], 1.0f);
    float rc = 1.0f / cnt;
    for (int i = j; i < NH; i += H1)
        sh_in[i] = fmaf(g_S[g * NH + i] * rc, g_scale[i], g_shift[i]);
    if (j < NF)
        sh_in[NH + j] = y_feat[g * NF + j];
    __syncthreads();

    // cleanup for next call: zero this graph's g_S row + strided node scratch
    for (int i = j; i < NH; i += H1)
        g_S[g * NH + i] = 0.0f;
    for (int i = g * H1 + j; i < NN; i += NG * H1) {
        g_degi[i] = 0;
        g_t[i] = 0.0f;
    }
    if (g == 0) { g_sumsq[j] = 0.0f; g_sumsq[j + H1] = 0.0f; }

    float acc = b1[j];
    #pragma unroll 8
    for (int cc = 0; cc < NH + NF; cc++)
        acc = fmaf(sh_in[cc], W1[cc * H1 + j], acc);
    sh_h[j] = gelu_f(acc);
    __syncthreads();

    if (j < 2) {
        float o = b2[j];
        #pragma unroll 8
        for (int k = 0; k < H1; k++)
            o = fmaf(sh_h[k], W2[k * 2 + j], o);
        out[g * 2 + j] = 1.0f / (1.0f + expf(-o));
    }
}

// ---------------- launch ------------------------------------------------------
extern "C" void kernel_launch(void* const* d_in, const int* in_sizes, int n_in,
                              void* d_out, int out_size)
{
    const float* x       = (const float*)d_in[0];
    const int*   eidx    = (const int*)  d_in[1];   // [2, NE]
    const int*   batch   = (const int*)  d_in[2];
    const float* y_feat  = (const float*)d_in[3];
    const float* W_conv  = (const float*)d_in[4];
    const float* b_conv  = (const float*)d_in[5];
    const float* gamma   = (const float*)d_in[6];
    const float* beta    = (const float*)d_in[7];
    const float* W1      = (const float*)d_in[8];
    const float* b1      = (const float*)d_in[9];
    const float* W2      = (const float*)d_in[10];
    const float* b2      = (const float*)d_in[11];
    float* out = (float*)d_out;

    const int* src = eidx;
    const int* dst = eidx + NE;

    deg_kernel<<<(NE / 16 + 255) / 256, 256>>>(dst);
    node_prep_kernel<<<(NN + 255) / 256, 256>>>(x);
    scatter_kernel<<<(NE / 8 + 255) / 256, 256>>>(src, dst);
    node_channel_kernel<<<NC_BLOCKS, NC_THREADS>>>(batch, W_conv, b_conv, gamma, beta);
    mlp_kernel<<<NG, H1>>>(y_feat, W1, b1, W2, b2, out);
}